// round 5
// baseline (speedup 1.0000x reference)
#include <cuda_runtime.h>
#include <cuda_fp16.h>
#include <cfloat>

// Fixed problem shape: img_features (1, 128, 224, 224) fp32, points (N,3), N<=1M.
#define C_CH   128
#define IMG    224
#define NPIX   (IMG * IMG)          // 50176
#define MAXPTS (1 << 20)
#define PBLK   (NPIX / 32)          // 1568 pixel-tiles for transpose

// Scratch (static device globals — no allocation at runtime).
__device__ float2 g_xy[MAXPTS];                 // transformed (x,y) per point, 8 MB
__device__ __half g_fmapT[NPIX * C_CH];         // feature map transposed to (x,y,c), fp16, 12.8 MB
__device__ int4   g_off[MAXPTS];                // per-point gather offsets (uint2 units)
__device__ float4 g_w[MAXPTS];                  // per-point bilinear weights (w11,w21,w12,w22)
__device__ int    g_minx, g_maxx, g_miny, g_maxy;   // ordered-int encoded float min/max

// Monotonic float<->int encoding for atomic min/max on floats.
__device__ __forceinline__ int f2oi(float f) {
    int i = __float_as_int(f);
    return (i >= 0) ? i : (i ^ 0x7fffffff);
}
__device__ __forceinline__ float oi2f(int i) {
    return __int_as_float((i >= 0) ? i : (i ^ 0x7fffffff));
}

__global__ void init_minmax_kernel() {
    g_minx = 0x7fffffff;            // +inf ordered
    g_miny = 0x7fffffff;
    g_maxx = 0x80000000;            // -inf ordered
    g_maxy = 0x80000000;
}

// Fused pass: blocks [0, nT) do the point transform + min/max reduce;
// blocks [nT, nT + 4*PBLK) do the feature-map transpose (independent data).
__global__ void fused_tt_kernel(const float* __restrict__ pts,
                                const float* __restrict__ Rm,
                                const float* __restrict__ Tv,
                                const float* __restrict__ img,
                                int n, int nT) {
    __shared__ float tile[32][33];      // transpose tile (also covers reduce scratch)
    __shared__ float s0[8], s1[8], s2[8], s3[8];

    if (blockIdx.x >= nT) {
        // ---- transpose (C, P) -> (P, C), fp32 -> fp16 ----
        int bid = blockIdx.x - nT;
        int p0 = (bid % PBLK) * 32;
        int c0 = (bid / PBLK) * 32;
        int tx = threadIdx.x & 31;
        int ty = threadIdx.x >> 5;       // 0..7

        #pragma unroll
        for (int dy = 0; dy < 32; dy += 8)
            tile[ty + dy][tx] = img[(size_t)(c0 + ty + dy) * NPIX + (p0 + tx)];
        __syncthreads();

        #pragma unroll
        for (int dy = 0; dy < 32; dy += 8)
            g_fmapT[(size_t)(p0 + ty + dy) * C_CH + (c0 + tx)] =
                __float2half_rn(tile[tx][ty + dy]);
        return;
    }

    // ---- transform: p = points @ R + T (x,y only) + global min/max ----
    // Rounding pinned to XLA's loop emitter (NO fp contraction):
    //   x = ((rn(p0*r0) + rn(p1*r3)) + rn(p2*r6)) + T — every op individually rounded.
    int i = blockIdx.x * blockDim.x + threadIdx.x;

    float lminx =  FLT_MAX, lmaxx = -FLT_MAX;
    float lminy =  FLT_MAX, lmaxy = -FLT_MAX;

    if (i < n) {
        float p0 = pts[3 * i + 0];
        float p1 = pts[3 * i + 1];
        float p2 = pts[3 * i + 2];
        float x = __fadd_rn(
                      __fadd_rn(
                          __fadd_rn(__fmul_rn(p0, Rm[0]), __fmul_rn(p1, Rm[3])),
                          __fmul_rn(p2, Rm[6])),
                      Tv[0]);
        float y = __fadd_rn(
                      __fadd_rn(
                          __fadd_rn(__fmul_rn(p0, Rm[1]), __fmul_rn(p1, Rm[4])),
                          __fmul_rn(p2, Rm[7])),
                      Tv[1]);
        g_xy[i] = make_float2(x, y);
        lminx = x; lmaxx = x;
        lminy = y; lmaxy = y;
    }

    #pragma unroll
    for (int o = 16; o > 0; o >>= 1) {
        lminx = fminf(lminx, __shfl_xor_sync(0xffffffffu, lminx, o));
        lmaxx = fmaxf(lmaxx, __shfl_xor_sync(0xffffffffu, lmaxx, o));
        lminy = fminf(lminy, __shfl_xor_sync(0xffffffffu, lminy, o));
        lmaxy = fmaxf(lmaxy, __shfl_xor_sync(0xffffffffu, lmaxy, o));
    }

    int wid  = threadIdx.x >> 5;
    int lane = threadIdx.x & 31;
    if (lane == 0) { s0[wid] = lminx; s1[wid] = lmaxx; s2[wid] = lminy; s3[wid] = lmaxy; }
    __syncthreads();

    if (threadIdx.x == 0) {
        float a = s0[0], b = s1[0], c = s2[0], d = s3[0];
        #pragma unroll
        for (int k = 1; k < 8; k++) {
            a = fminf(a, s0[k]); b = fmaxf(b, s1[k]);
            c = fminf(c, s2[k]); d = fmaxf(d, s3[k]);
        }
        atomicMin(&g_minx, f2oi(a));
        atomicMax(&g_maxx, f2oi(b));
        atomicMin(&g_miny, f2oi(c));
        atomicMax(&g_maxy, f2oi(d));
    }
}

// Per-point setup, one thread per point. All rounding pinned (bit-exact path).
__global__ void prep_kernel(int n) {
    int i = blockIdx.x * blockDim.x + threadIdx.x;
    if (i >= n) return;

    float minx = oi2f(g_minx), maxx = oi2f(g_maxx);
    float miny = oi2f(g_miny), maxy = oi2f(g_maxy);
    // IEEE division — approximate-reciprocal divide flips floor/ceil bins.
    float sx = __fdiv_rn(223.99f, __fsub_rn(maxx, minx));
    float sy = __fdiv_rn(223.99f, __fsub_rn(maxy, miny));

    float2 xy = g_xy[i];
    float xv = __fmul_rn(__fsub_rn(xy.x, minx), sx);
    float yv = __fmul_rn(__fsub_rn(xy.y, miny), sy);

    int x1 = (int)floorf(xv);
    int x2 = min((int)ceilf(xv), IMG - 1);
    int y1 = (int)floorf(yv);
    int y2 = min((int)ceilf(yv), IMG - 1);

    float x1f = (float)x1, x2f = (float)x2;
    float y1f = (float)y1, y2f = (float)y2;
    float4 w;
    w.x = __fmul_rn(__fsub_rn(x2f, xv), __fsub_rn(y2f, yv));  // w11
    w.y = __fmul_rn(__fsub_rn(xv, x1f), __fsub_rn(y2f, yv));  // w21
    w.z = __fmul_rn(__fsub_rn(x2f, xv), __fsub_rn(yv, y1f));  // w12
    w.w = __fmul_rn(__fsub_rn(xv, x1f), __fsub_rn(yv, y1f));  // w22

    int r1 = x1 * IMG, r2 = x2 * IMG;
    int4 off;                      // offsets in uint2 (4-halves) units
    off.x = (r1 + y1) * 32;        // Q11
    off.y = (r2 + y1) * 32;        // Q21
    off.z = (r1 + y2) * 32;        // Q12
    off.w = (r2 + y2) * 32;        // Q22
    g_off[i] = off;
    g_w[i]   = w;
}

// Gather: one warp per point; lane handles 4 channels (8B fp16 load, 16B fp32 store).
__global__ void gather_kernel(float* __restrict__ out, int n) {
    int gtid = blockIdx.x * blockDim.x + threadIdx.x;
    int pi   = gtid >> 5;
    int lane = gtid & 31;
    if (pi >= n) return;

    int4   off = g_off[pi];   // uniform across warp -> broadcast
    float4 w   = g_w[pi];

    const uint2* __restrict__ f = (const uint2*)g_fmapT;
    uint2 a11 = f[off.x + lane];
    uint2 a21 = f[off.y + lane];
    uint2 a12 = f[off.z + lane];
    uint2 a22 = f[off.w + lane];

    float2 q11a = __half22float2(*(const __half2*)&a11.x);
    float2 q11b = __half22float2(*(const __half2*)&a11.y);
    float2 q21a = __half22float2(*(const __half2*)&a21.x);
    float2 q21b = __half22float2(*(const __half2*)&a21.y);
    float2 q12a = __half22float2(*(const __half2*)&a12.x);
    float2 q12b = __half22float2(*(const __half2*)&a12.y);
    float2 q22a = __half22float2(*(const __half2*)&a22.x);
    float2 q22b = __half22float2(*(const __half2*)&a22.y);

    // reference order, no contraction: ((Q11*w11 + Q21*w21) + Q12*w12) + Q22*w22
    float4 o;
    o.x = __fadd_rn(__fadd_rn(__fadd_rn(__fmul_rn(q11a.x, w.x), __fmul_rn(q21a.x, w.y)),
                              __fmul_rn(q12a.x, w.z)), __fmul_rn(q22a.x, w.w));
    o.y = __fadd_rn(__fadd_rn(__fadd_rn(__fmul_rn(q11a.y, w.x), __fmul_rn(q21a.y, w.y)),
                              __fmul_rn(q12a.y, w.z)), __fmul_rn(q22a.y, w.w));
    o.z = __fadd_rn(__fadd_rn(__fadd_rn(__fmul_rn(q11b.x, w.x), __fmul_rn(q21b.x, w.y)),
                              __fmul_rn(q12b.x, w.z)), __fmul_rn(q22b.x, w.w));
    o.w = __fadd_rn(__fadd_rn(__fadd_rn(__fmul_rn(q11b.y, w.x), __fmul_rn(q21b.y, w.y)),
                              __fmul_rn(q12b.y, w.z)), __fmul_rn(q22b.y, w.w));

    ((float4*)out)[(size_t)pi * 32 + lane] = o;
}

extern "C" void kernel_launch(void* const* d_in, const int* in_sizes, int n_in,
                              void* d_out, int out_size) {
    const float* img = (const float*)d_in[0];   // (1, 128, 224, 224)
    const float* pts = (const float*)d_in[1];   // (N, 3)
    const float* R   = (const float*)d_in[2];   // (3, 3)
    const float* T   = (const float*)d_in[3];   // (3,)
    float* out = (float*)d_out;                  // (1, N, 128)

    int n = in_sizes[1] / 3;
    int nT = (n + 255) / 256;                    // transform blocks
    int nTrans = PBLK * (C_CH / 32);             // 1568 * 4 = 6272 transpose blocks

    init_minmax_kernel<<<1, 1>>>();
    fused_tt_kernel<<<nT + nTrans, 256>>>(pts, R, T, img, n, nT);
    prep_kernel<<<(n + 255) / 256, 256>>>(n);

    // 8 warps per block -> 8 points per block
    int blocks = (n + 7) / 8;
    gather_kernel<<<blocks, 256>>>(out, n);
}

// round 6
// speedup vs baseline: 1.1755x; 1.1755x over previous
#include <cuda_runtime.h>
#include <cuda_fp16.h>
#include <cfloat>

// Fixed problem shape: img_features (1, 128, 224, 224) fp32, points (N,3), N<=1M.
#define C_CH   128
#define IMG    224
#define NPIX   (IMG * IMG)          // 50176
#define MAXPTS (1 << 20)
#define PBLK   (NPIX / 32)          // 1568 pixel-tiles for transpose

// Scratch (static device globals — no allocation at runtime).
__device__ float2 g_xy[MAXPTS];                 // transformed (x,y) per point, 8 MB
__device__ __half g_fmapT[NPIX * C_CH];         // feature map transposed to (x,y,c), fp16, 12.8 MB
__device__ int4   g_off[MAXPTS];                // per-point gather offsets (uint4 units)
__device__ float4 g_w[MAXPTS];                  // per-point bilinear weights (w11,w21,w12,w22)
__device__ int    g_minx, g_maxx, g_miny, g_maxy;   // ordered-int encoded float min/max

// Monotonic float<->int encoding for atomic min/max on floats.
__device__ __forceinline__ int f2oi(float f) {
    int i = __float_as_int(f);
    return (i >= 0) ? i : (i ^ 0x7fffffff);
}
__device__ __forceinline__ float oi2f(int i) {
    return __int_as_float((i >= 0) ? i : (i ^ 0x7fffffff));
}

__global__ void init_minmax_kernel() {
    g_minx = 0x7fffffff;            // +inf ordered
    g_miny = 0x7fffffff;
    g_maxx = 0x80000000;            // -inf ordered
    g_maxy = 0x80000000;
}

// Fused pass: blocks [0, nT) do the point transform + min/max reduce;
// blocks [nT, nT + 4*PBLK) do the feature-map transpose (independent data).
__global__ void fused_tt_kernel(const float* __restrict__ pts,
                                const float* __restrict__ Rm,
                                const float* __restrict__ Tv,
                                const float* __restrict__ img,
                                int n, int nT) {
    __shared__ float tile[32][33];
    __shared__ float s0[8], s1[8], s2[8], s3[8];

    if (blockIdx.x >= nT) {
        // ---- transpose (C, P) -> (P, C), fp32 -> fp16 ----
        int bid = blockIdx.x - nT;
        int p0 = (bid % PBLK) * 32;
        int c0 = (bid / PBLK) * 32;
        int tx = threadIdx.x & 31;
        int ty = threadIdx.x >> 5;       // 0..7

        #pragma unroll
        for (int dy = 0; dy < 32; dy += 8)
            tile[ty + dy][tx] = img[(size_t)(c0 + ty + dy) * NPIX + (p0 + tx)];
        __syncthreads();

        #pragma unroll
        for (int dy = 0; dy < 32; dy += 8)
            g_fmapT[(size_t)(p0 + ty + dy) * C_CH + (c0 + tx)] =
                __float2half_rn(tile[tx][ty + dy]);
        return;
    }

    // ---- transform: p = points @ R + T (x,y only) + global min/max ----
    // Rounding pinned to XLA's loop emitter (NO fp contraction).
    int i = blockIdx.x * blockDim.x + threadIdx.x;

    float lminx =  FLT_MAX, lmaxx = -FLT_MAX;
    float lminy =  FLT_MAX, lmaxy = -FLT_MAX;

    if (i < n) {
        float p0 = pts[3 * i + 0];
        float p1 = pts[3 * i + 1];
        float p2 = pts[3 * i + 2];
        float x = __fadd_rn(
                      __fadd_rn(
                          __fadd_rn(__fmul_rn(p0, Rm[0]), __fmul_rn(p1, Rm[3])),
                          __fmul_rn(p2, Rm[6])),
                      Tv[0]);
        float y = __fadd_rn(
                      __fadd_rn(
                          __fadd_rn(__fmul_rn(p0, Rm[1]), __fmul_rn(p1, Rm[4])),
                          __fmul_rn(p2, Rm[7])),
                      Tv[1]);
        g_xy[i] = make_float2(x, y);
        lminx = x; lmaxx = x;
        lminy = y; lmaxy = y;
    }

    #pragma unroll
    for (int o = 16; o > 0; o >>= 1) {
        lminx = fminf(lminx, __shfl_xor_sync(0xffffffffu, lminx, o));
        lmaxx = fmaxf(lmaxx, __shfl_xor_sync(0xffffffffu, lmaxx, o));
        lminy = fminf(lminy, __shfl_xor_sync(0xffffffffu, lminy, o));
        lmaxy = fmaxf(lmaxy, __shfl_xor_sync(0xffffffffu, lmaxy, o));
    }

    int wid  = threadIdx.x >> 5;
    int lane = threadIdx.x & 31;
    if (lane == 0) { s0[wid] = lminx; s1[wid] = lmaxx; s2[wid] = lminy; s3[wid] = lmaxy; }
    __syncthreads();

    if (threadIdx.x == 0) {
        float a = s0[0], b = s1[0], c = s2[0], d = s3[0];
        #pragma unroll
        for (int k = 1; k < 8; k++) {
            a = fminf(a, s0[k]); b = fmaxf(b, s1[k]);
            c = fminf(c, s2[k]); d = fmaxf(d, s3[k]);
        }
        atomicMin(&g_minx, f2oi(a));
        atomicMax(&g_maxx, f2oi(b));
        atomicMin(&g_miny, f2oi(c));
        atomicMax(&g_maxy, f2oi(d));
    }
}

// Per-point setup, one thread per point. All rounding pinned (bit-exact path).
__global__ void prep_kernel(int n) {
    int i = blockIdx.x * blockDim.x + threadIdx.x;
    if (i >= n) return;

    float minx = oi2f(g_minx), maxx = oi2f(g_maxx);
    float miny = oi2f(g_miny), maxy = oi2f(g_maxy);
    float sx = __fdiv_rn(223.99f, __fsub_rn(maxx, minx));
    float sy = __fdiv_rn(223.99f, __fsub_rn(maxy, miny));

    float2 xy = g_xy[i];
    float xv = __fmul_rn(__fsub_rn(xy.x, minx), sx);
    float yv = __fmul_rn(__fsub_rn(xy.y, miny), sy);

    int x1 = (int)floorf(xv);
    int x2 = min((int)ceilf(xv), IMG - 1);
    int y1 = (int)floorf(yv);
    int y2 = min((int)ceilf(yv), IMG - 1);

    float x1f = (float)x1, x2f = (float)x2;
    float y1f = (float)y1, y2f = (float)y2;
    float4 w;
    w.x = __fmul_rn(__fsub_rn(x2f, xv), __fsub_rn(y2f, yv));  // w11
    w.y = __fmul_rn(__fsub_rn(xv, x1f), __fsub_rn(y2f, yv));  // w21
    w.z = __fmul_rn(__fsub_rn(x2f, xv), __fsub_rn(yv, y1f));  // w12
    w.w = __fmul_rn(__fsub_rn(xv, x1f), __fsub_rn(yv, y1f));  // w22

    int r1 = x1 * IMG, r2 = x2 * IMG;
    int4 off;                      // offsets in uint4 (8-halves) units
    off.x = (r1 + y1) * 16;        // Q11
    off.y = (r2 + y1) * 16;        // Q21
    off.z = (r1 + y2) * 16;        // Q12
    off.w = (r2 + y2) * 16;        // Q22
    g_off[i] = off;
    g_w[i]   = w;
}

// reference order, no contraction: ((Q11*w11 + Q21*w21) + Q12*w12) + Q22*w22
__device__ __forceinline__ float bil(float a, float b, float c, float d, float4 w) {
    return __fadd_rn(__fadd_rn(__fadd_rn(__fmul_rn(a, w.x), __fmul_rn(b, w.y)),
                               __fmul_rn(c, w.z)), __fmul_rn(d, w.w));
}

// Gather: half-warp per point (2 points per warp). Lane handles 8 channels:
// one LDG.128 (16 fp16 bytes) per corner per half-warp, 2 STG.128 per point-pair.
__global__ void gather_kernel(float* __restrict__ out, int n) {
    int gtid = blockIdx.x * blockDim.x + threadIdx.x;
    int warp = gtid >> 5;
    int lane = gtid & 31;
    int h    = lane & 15;               // channel-group within point
    int pi   = warp * 2 + (lane >> 4);  // point index
    if (pi >= n) return;

    int4   off = g_off[pi];             // 2 addresses per warp
    float4 w   = g_w[pi];

    const uint4* __restrict__ f = (const uint4*)g_fmapT;
    uint4 a11 = f[off.x + h];
    uint4 a21 = f[off.y + h];
    uint4 a12 = f[off.z + h];
    uint4 a22 = f[off.w + h];

    float2 q11[4], q21[4], q12[4], q22[4];
    q11[0] = __half22float2(*(const __half2*)&a11.x);
    q11[1] = __half22float2(*(const __half2*)&a11.y);
    q11[2] = __half22float2(*(const __half2*)&a11.z);
    q11[3] = __half22float2(*(const __half2*)&a11.w);
    q21[0] = __half22float2(*(const __half2*)&a21.x);
    q21[1] = __half22float2(*(const __half2*)&a21.y);
    q21[2] = __half22float2(*(const __half2*)&a21.z);
    q21[3] = __half22float2(*(const __half2*)&a21.w);
    q12[0] = __half22float2(*(const __half2*)&a12.x);
    q12[1] = __half22float2(*(const __half2*)&a12.y);
    q12[2] = __half22float2(*(const __half2*)&a12.z);
    q12[3] = __half22float2(*(const __half2*)&a12.w);
    q22[0] = __half22float2(*(const __half2*)&a22.x);
    q22[1] = __half22float2(*(const __half2*)&a22.y);
    q22[2] = __half22float2(*(const __half2*)&a22.z);
    q22[3] = __half22float2(*(const __half2*)&a22.w);

    float4 o0, o1;
    o0.x = bil(q11[0].x, q21[0].x, q12[0].x, q22[0].x, w);
    o0.y = bil(q11[0].y, q21[0].y, q12[0].y, q22[0].y, w);
    o0.z = bil(q11[1].x, q21[1].x, q12[1].x, q22[1].x, w);
    o0.w = bil(q11[1].y, q21[1].y, q12[1].y, q22[1].y, w);
    o1.x = bil(q11[2].x, q21[2].x, q12[2].x, q22[2].x, w);
    o1.y = bil(q11[2].y, q21[2].y, q12[2].y, q22[2].y, w);
    o1.z = bil(q11[3].x, q21[3].x, q12[3].x, q22[3].x, w);
    o1.w = bil(q11[3].y, q21[3].y, q12[3].y, q22[3].y, w);

    // out channels [8h, 8h+8) of point pi; evict-first to spare L2 for the fmap
    float4* op = (float4*)out + (size_t)pi * 32 + 2 * h;
    __stcs(op,     o0);
    __stcs(op + 1, o1);
}

extern "C" void kernel_launch(void* const* d_in, const int* in_sizes, int n_in,
                              void* d_out, int out_size) {
    const float* img = (const float*)d_in[0];   // (1, 128, 224, 224)
    const float* pts = (const float*)d_in[1];   // (N, 3)
    const float* R   = (const float*)d_in[2];   // (3, 3)
    const float* T   = (const float*)d_in[3];   // (3,)
    float* out = (float*)d_out;                  // (1, N, 128)

    int n = in_sizes[1] / 3;
    int nT = (n + 255) / 256;                    // transform blocks
    int nTrans = PBLK * (C_CH / 32);             // 1568 * 4 = 6272 transpose blocks

    init_minmax_kernel<<<1, 1>>>();
    fused_tt_kernel<<<nT + nTrans, 256>>>(pts, R, T, img, n, nT);
    prep_kernel<<<(n + 255) / 256, 256>>>(n);

    // 16 points per 256-thread block (2 per warp)
    int blocks = (n + 15) / 16;
    gather_kernel<<<blocks, 256>>>(out, n);
}

// round 7
// speedup vs baseline: 1.2692x; 1.0797x over previous
#include <cuda_runtime.h>
#include <cuda_fp16.h>
#include <cfloat>

// Fixed problem shape: img_features (1, 128, 224, 224) fp32, points (N,3), N<=1M.
#define C_CH   128
#define IMG    224
#define NPIX   (IMG * IMG)          // 50176
#define MAXPTS (1 << 20)
#define PBLK   (NPIX / 32)          // 1568 pixel-tiles for transpose

// Scratch (static device globals — no allocation at runtime).
__device__ float2 g_xy[MAXPTS];                 // transformed (x,y) per point, 8 MB
__device__ __half g_fmapT[NPIX * C_CH];         // feature map transposed to (x,y,c), fp16, 12.8 MB
__device__ int    g_minx, g_maxx, g_miny, g_maxy;   // ordered-int encoded float min/max

// Monotonic float<->int encoding for atomic min/max on floats.
__device__ __forceinline__ int f2oi(float f) {
    int i = __float_as_int(f);
    return (i >= 0) ? i : (i ^ 0x7fffffff);
}
__device__ __forceinline__ float oi2f(int i) {
    return __int_as_float((i >= 0) ? i : (i ^ 0x7fffffff));
}

__global__ void init_minmax_kernel() {
    g_minx = 0x7fffffff;            // +inf ordered
    g_miny = 0x7fffffff;
    g_maxx = 0x80000000;            // -inf ordered
    g_maxy = 0x80000000;
}

// Fused pass: blocks [0, nT) do the point transform + min/max reduce;
// blocks [nT, nT + 4*PBLK) do the feature-map transpose (independent data).
__global__ void fused_tt_kernel(const float* __restrict__ pts,
                                const float* __restrict__ Rm,
                                const float* __restrict__ Tv,
                                const float* __restrict__ img,
                                int n, int nT) {
    __shared__ float tile[32][33];
    __shared__ float s0[8], s1[8], s2[8], s3[8];

    if (blockIdx.x >= nT) {
        // ---- transpose (C, P) -> (P, C), fp32 -> fp16 ----
        int bid = blockIdx.x - nT;
        int p0 = (bid % PBLK) * 32;
        int c0 = (bid / PBLK) * 32;
        int tx = threadIdx.x & 31;
        int ty = threadIdx.x >> 5;       // 0..7

        #pragma unroll
        for (int dy = 0; dy < 32; dy += 8)
            tile[ty + dy][tx] = img[(size_t)(c0 + ty + dy) * NPIX + (p0 + tx)];
        __syncthreads();

        #pragma unroll
        for (int dy = 0; dy < 32; dy += 8)
            g_fmapT[(size_t)(p0 + ty + dy) * C_CH + (c0 + tx)] =
                __float2half_rn(tile[tx][ty + dy]);
        return;
    }

    // ---- transform: p = points @ R + T (x,y only) + global min/max ----
    // Rounding pinned to XLA's loop emitter (NO fp contraction).
    int i = blockIdx.x * blockDim.x + threadIdx.x;

    float lminx =  FLT_MAX, lmaxx = -FLT_MAX;
    float lminy =  FLT_MAX, lmaxy = -FLT_MAX;

    if (i < n) {
        float p0 = pts[3 * i + 0];
        float p1 = pts[3 * i + 1];
        float p2 = pts[3 * i + 2];
        float x = __fadd_rn(
                      __fadd_rn(
                          __fadd_rn(__fmul_rn(p0, Rm[0]), __fmul_rn(p1, Rm[3])),
                          __fmul_rn(p2, Rm[6])),
                      Tv[0]);
        float y = __fadd_rn(
                      __fadd_rn(
                          __fadd_rn(__fmul_rn(p0, Rm[1]), __fmul_rn(p1, Rm[4])),
                          __fmul_rn(p2, Rm[7])),
                      Tv[1]);
        g_xy[i] = make_float2(x, y);
        lminx = x; lmaxx = x;
        lminy = y; lmaxy = y;
    }

    #pragma unroll
    for (int o = 16; o > 0; o >>= 1) {
        lminx = fminf(lminx, __shfl_xor_sync(0xffffffffu, lminx, o));
        lmaxx = fmaxf(lmaxx, __shfl_xor_sync(0xffffffffu, lmaxx, o));
        lminy = fminf(lminy, __shfl_xor_sync(0xffffffffu, lminy, o));
        lmaxy = fmaxf(lmaxy, __shfl_xor_sync(0xffffffffu, lmaxy, o));
    }

    int wid  = threadIdx.x >> 5;
    int lane = threadIdx.x & 31;
    if (lane == 0) { s0[wid] = lminx; s1[wid] = lmaxx; s2[wid] = lminy; s3[wid] = lmaxy; }
    __syncthreads();

    if (threadIdx.x == 0) {
        float a = s0[0], b = s1[0], c = s2[0], d = s3[0];
        #pragma unroll
        for (int k = 1; k < 8; k++) {
            a = fminf(a, s0[k]); b = fmaxf(b, s1[k]);
            c = fminf(c, s2[k]); d = fmaxf(d, s3[k]);
        }
        atomicMin(&g_minx, f2oi(a));
        atomicMax(&g_maxx, f2oi(b));
        atomicMin(&g_miny, f2oi(c));
        atomicMax(&g_maxy, f2oi(d));
    }
}

// reference order, no contraction: ((Q11*w11 + Q21*w21) + Q12*w12) + Q22*w22
__device__ __forceinline__ float bil(float a, float b, float c, float d, float4 w) {
    return __fadd_rn(__fadd_rn(__fadd_rn(__fmul_rn(a, w.x), __fmul_rn(b, w.y)),
                               __fmul_rn(c, w.z)), __fmul_rn(d, w.w));
}

// Gather with inlined per-point setup: half-warp per point (2 points per warp).
// Setup is pure FMA/ALU/MUFU (overlaps the saturated LSU pipe); memory instrs
// per warp: 1 LDG.64 (xy) + 4 gather LDG.128 + 2 STG.128.
__global__ void gather_kernel(float* __restrict__ out, int n) {
    int gtid = blockIdx.x * blockDim.x + threadIdx.x;
    int warp = gtid >> 5;
    int lane = gtid & 31;
    int h    = lane & 15;               // channel-group within point
    int pi   = warp * 2 + (lane >> 4);  // point index
    if (pi >= n) return;

    // ---- per-point setup (verbatim pinned rounding from the prep pass) ----
    float minx = oi2f(g_minx), maxx = oi2f(g_maxx);
    float miny = oi2f(g_miny), maxy = oi2f(g_maxy);
    // IEEE division — approximate-reciprocal divide flips floor/ceil bins.
    float sx = __fdiv_rn(223.99f, __fsub_rn(maxx, minx));
    float sy = __fdiv_rn(223.99f, __fsub_rn(maxy, miny));

    float2 xy = g_xy[pi];
    float xv = __fmul_rn(__fsub_rn(xy.x, minx), sx);
    float yv = __fmul_rn(__fsub_rn(xy.y, miny), sy);

    int x1 = (int)floorf(xv);
    int x2 = min((int)ceilf(xv), IMG - 1);
    int y1 = (int)floorf(yv);
    int y2 = min((int)ceilf(yv), IMG - 1);

    float x1f = (float)x1, x2f = (float)x2;
    float y1f = (float)y1, y2f = (float)y2;
    float4 w;
    w.x = __fmul_rn(__fsub_rn(x2f, xv), __fsub_rn(y2f, yv));  // w11
    w.y = __fmul_rn(__fsub_rn(xv, x1f), __fsub_rn(y2f, yv));  // w21
    w.z = __fmul_rn(__fsub_rn(x2f, xv), __fsub_rn(yv, y1f));  // w12
    w.w = __fmul_rn(__fsub_rn(xv, x1f), __fsub_rn(yv, y1f));  // w22

    int r1 = x1 * IMG, r2 = x2 * IMG;
    int o11 = (r1 + y1) * 16;           // offsets in uint4 (8-halves) units
    int o21 = (r2 + y1) * 16;
    int o12 = (r1 + y2) * 16;
    int o22 = (r2 + y2) * 16;

    // ---- gather + combine ----
    const uint4* __restrict__ f = (const uint4*)g_fmapT;
    uint4 a11 = f[o11 + h];
    uint4 a21 = f[o21 + h];
    uint4 a12 = f[o12 + h];
    uint4 a22 = f[o22 + h];

    float2 q11[4], q21[4], q12[4], q22[4];
    q11[0] = __half22float2(*(const __half2*)&a11.x);
    q11[1] = __half22float2(*(const __half2*)&a11.y);
    q11[2] = __half22float2(*(const __half2*)&a11.z);
    q11[3] = __half22float2(*(const __half2*)&a11.w);
    q21[0] = __half22float2(*(const __half2*)&a21.x);
    q21[1] = __half22float2(*(const __half2*)&a21.y);
    q21[2] = __half22float2(*(const __half2*)&a21.z);
    q21[3] = __half22float2(*(const __half2*)&a21.w);
    q12[0] = __half22float2(*(const __half2*)&a12.x);
    q12[1] = __half22float2(*(const __half2*)&a12.y);
    q12[2] = __half22float2(*(const __half2*)&a12.z);
    q12[3] = __half22float2(*(const __half2*)&a12.w);
    q22[0] = __half22float2(*(const __half2*)&a22.x);
    q22[1] = __half22float2(*(const __half2*)&a22.y);
    q22[2] = __half22float2(*(const __half2*)&a22.z);
    q22[3] = __half22float2(*(const __half2*)&a22.w);

    float4 o0, o1;
    o0.x = bil(q11[0].x, q21[0].x, q12[0].x, q22[0].x, w);
    o0.y = bil(q11[0].y, q21[0].y, q12[0].y, q22[0].y, w);
    o0.z = bil(q11[1].x, q21[1].x, q12[1].x, q22[1].x, w);
    o0.w = bil(q11[1].y, q21[1].y, q12[1].y, q22[1].y, w);
    o1.x = bil(q11[2].x, q21[2].x, q12[2].x, q22[2].x, w);
    o1.y = bil(q11[2].y, q21[2].y, q12[2].y, q22[2].y, w);
    o1.z = bil(q11[3].x, q21[3].x, q12[3].x, q22[3].x, w);
    o1.w = bil(q11[3].y, q21[3].y, q12[3].y, q22[3].y, w);

    // out channels [8h, 8h+8) of point pi; evict-first to spare L2 for the fmap
    float4* op = (float4*)out + (size_t)pi * 32 + 2 * h;
    __stcs(op,     o0);
    __stcs(op + 1, o1);
}

extern "C" void kernel_launch(void* const* d_in, const int* in_sizes, int n_in,
                              void* d_out, int out_size) {
    const float* img = (const float*)d_in[0];   // (1, 128, 224, 224)
    const float* pts = (const float*)d_in[1];   // (N, 3)
    const float* R   = (const float*)d_in[2];   // (3, 3)
    const float* T   = (const float*)d_in[3];   // (3,)
    float* out = (float*)d_out;                  // (1, N, 128)

    int n = in_sizes[1] / 3;
    int nT = (n + 255) / 256;                    // transform blocks
    int nTrans = PBLK * (C_CH / 32);             // 1568 * 4 = 6272 transpose blocks

    init_minmax_kernel<<<1, 1>>>();
    fused_tt_kernel<<<nT + nTrans, 256>>>(pts, R, T, img, n, nT);

    // 16 points per 256-thread block (2 per warp)
    int blocks = (n + 15) / 16;
    gather_kernel<<<blocks, 256>>>(out, n);
}